// round 3
// baseline (speedup 1.0000x reference)
#include <cuda_runtime.h>

// Problem shapes (fixed per reference setup_inputs)
#define BB 32
#define HH 1024
#define WW 1024
#define TH 512
#define TW 512
#define SS 256
#define BAND_ROWS 16              // output rows per block
#define NBANDS (HH / BAND_ROWS)   // 64
#define NBLOCKS (NBANDS * BB)     // 2048

__device__ double g_img_sum = 0.0;
__device__ double g_stn_sum = 0.0;
__device__ unsigned int g_count = 0;

// One fused kernel. Block (band, b): computes MSE partial for 16 output rows of
// image b against the bilinearly-upsampled target. Blocks with band==0 also
// handle the 256 stations of batch b (one per thread). Last finishing block
// combines and writes the 3 outputs, then resets the global accumulators.
__global__ __launch_bounds__(256) void fused_kernel(const float* __restrict__ pred,
                                                    const float* __restrict__ tgt,
                                                    const int* __restrict__ pos,
                                                    const float* __restrict__ run,
                                                    float* __restrict__ out) {
    __shared__ float st[10][TW];   // 20 KB target row staging
    __shared__ float wsum[8];
    __shared__ float wsum2[8];

    const int band = blockIdx.x;   // 0..63
    const int b    = blockIdx.y;   // 0..31
    const int tid  = threadIdx.x;  // 0..255
    const int kbase = band * 8 - 1;

    // ---- Station loss (band==0 blocks only): issue gathers early ----
    float stn_val = 0.f;
    if (band == 0) {
        int idx = b * SS + tid;
        int px = pos[2 * idx];       // column
        int py = pos[2 * idx + 1];   // row
        const float* pb0 = pred + (size_t)b * HH * WW;
        float sum = 0.f;
        int cnt = 0;
#pragma unroll
        for (int dy = -1; dy <= 1; ++dy) {
            int y = py + dy;
            if ((unsigned)y < (unsigned)HH) {
#pragma unroll
                for (int dx = -1; dx <= 1; ++dx) {
                    int x = px + dx;
                    if ((unsigned)x < (unsigned)WW) {
                        sum += pb0[(size_t)y * WW + x];
                        cnt++;
                    }
                }
            }
        }
        float d = sum / (float)cnt - run[idx];
        stn_val = d * d;
    }

    // ---- Stage 10 target rows (row-clamped at image edges) ----
    const float* tb = tgt + (size_t)b * TH * TW;
#pragma unroll
    for (int i = 0; i < 5; ++i) {
        int idx = tid + i * 256;          // 0..1279 float4 slots
        int r   = idx >> 7;               // 0..9
        int c4  = (idx & 127) << 2;       // 0..508
        int k   = kbase + r;
        k = k < 0 ? 0 : (k > TH - 1 ? TH - 1 : k);
        float4 v = *(const float4*)(tb + (size_t)k * TW + c4);
        *(float4*)&st[r][c4] = v;
    }
    __syncthreads();

    // Column indices this thread needs (target cols 2t-1..2t+2, clamped)
    const int t = tid;
    int j0 = 2 * t - 1; if (j0 < 0) j0 = 0;
    const int j1 = 2 * t;
    const int j2 = 2 * t + 1;
    int j3 = 2 * t + 2; if (j3 > TW - 1) j3 = TW - 1;

    float a0 = st[0][j0], a1 = st[0][j1], a2 = st[0][j2], a3 = st[0][j3];
    float b0 = st[1][j0], b1 = st[1][j1], b2 = st[1][j2], b3 = st[1][j3];

    const float* pb = pred + ((size_t)b * HH + (size_t)band * BAND_ROWS) * WW + 4 * t;
    float acc = 0.f;

#pragma unroll
    for (int p = 0; p < 8; ++p) {
        float c0 = st[p + 2][j0], c1 = st[p + 2][j1];
        float c2 = st[p + 2][j2], c3 = st[p + 2][j3];

        // even output row 2p: 0.25*row(p) + 0.75*row(p+1)
        float4 pv = *(const float4*)(pb + (size_t)(2 * p) * WW);
        float v0 = 0.25f * a0 + 0.75f * b0;
        float v1 = 0.25f * a1 + 0.75f * b1;
        float v2 = 0.25f * a2 + 0.75f * b2;
        float v3 = 0.25f * a3 + 0.75f * b3;
        float d;
        d = pv.x - (0.25f * v0 + 0.75f * v1); acc = fmaf(d, d, acc);
        d = pv.y - (0.75f * v1 + 0.25f * v2); acc = fmaf(d, d, acc);
        d = pv.z - (0.25f * v1 + 0.75f * v2); acc = fmaf(d, d, acc);
        d = pv.w - (0.75f * v2 + 0.25f * v3); acc = fmaf(d, d, acc);

        // odd output row 2p+1: 0.75*row(p+1) + 0.25*row(p+2)
        pv = *(const float4*)(pb + (size_t)(2 * p + 1) * WW);
        v0 = 0.75f * b0 + 0.25f * c0;
        v1 = 0.75f * b1 + 0.25f * c1;
        v2 = 0.75f * b2 + 0.25f * c2;
        v3 = 0.75f * b3 + 0.25f * c3;
        d = pv.x - (0.25f * v0 + 0.75f * v1); acc = fmaf(d, d, acc);
        d = pv.y - (0.75f * v1 + 0.25f * v2); acc = fmaf(d, d, acc);
        d = pv.z - (0.25f * v1 + 0.75f * v2); acc = fmaf(d, d, acc);
        d = pv.w - (0.75f * v2 + 0.25f * v3); acc = fmaf(d, d, acc);

        a0 = b0; a1 = b1; a2 = b2; a3 = b3;
        b0 = c0; b1 = c1; b2 = c2; b3 = c3;
    }

    // ---- Block reductions ----
#pragma unroll
    for (int o = 16; o > 0; o >>= 1) {
        acc     += __shfl_xor_sync(0xffffffffu, acc, o);
        stn_val += __shfl_xor_sync(0xffffffffu, stn_val, o);
    }
    int lane = tid & 31, wid = tid >> 5;
    if (lane == 0) { wsum[wid] = acc; wsum2[wid] = stn_val; }
    __syncthreads();

    if (tid == 0) {
        float s = 0.f, s2 = 0.f;
#pragma unroll
        for (int i = 0; i < 8; ++i) { s += wsum[i]; s2 += wsum2[i]; }
        atomicAdd(&g_img_sum, (double)s);
        if (band == 0) atomicAdd(&g_stn_sum, (double)s2);
        __threadfence();
        unsigned int old = atomicAdd(&g_count, 1u);
        if (old == NBLOCKS - 1) {
            // Last block: L2-coherent reads via atomic RMW of 0
            double img = atomicAdd(&g_img_sum, 0.0) / (double)((size_t)BB * HH * WW);
            double stn = atomicAdd(&g_stn_sum, 0.0) / (double)(BB * SS);
            out[0] = (float)(img + 0.5 * stn);  // IMAGE_W=1.0, STATION_W=0.5
            out[1] = (float)img;
            out[2] = (float)stn;
            // Reset for next graph replay (deterministic across calls)
            g_img_sum = 0.0;
            g_stn_sum = 0.0;
            __threadfence();
            g_count = 0u;
        }
    }
}

extern "C" void kernel_launch(void* const* d_in, const int* in_sizes, int n_in,
                              void* d_out, int out_size) {
    const float* pred = (const float*)d_in[0];   // (32,1,1024,1024) f32
    const float* tgt  = (const float*)d_in[1];   // (32,1,512,512) f32
    const int*   pos  = (const int*)d_in[2];     // (32,256,2) i32
    const float* run  = (const float*)d_in[3];   // (32,256) f32
    float* out = (float*)d_out;

    fused_kernel<<<dim3(NBANDS, BB), 256>>>(pred, tgt, pos, run, out);
}

// round 5
// speedup vs baseline: 1.1963x; 1.1963x over previous
#include <cuda_runtime.h>
#include <cstdint>

// Problem shapes (fixed per reference setup_inputs)
#define BB 32
#define HH 1024
#define WW 1024
#define TH 512
#define TW 512
#define SS 256
#define BAND_ROWS 16              // output rows per block
#define NBANDS (HH / BAND_ROWS)   // 64
#define NBLOCKS (NBANDS * BB)     // 2048

__device__ double g_img_sum = 0.0;
__device__ double g_stn_sum = 0.0;
__device__ unsigned int g_count = 0;

__device__ __forceinline__ void cp_async16(void* smem_dst, const void* gmem_src) {
    uint32_t s = (uint32_t)__cvta_generic_to_shared(smem_dst);
    asm volatile("cp.async.cg.shared.global [%0], [%1], 16;" :: "r"(s), "l"(gmem_src));
}

// One fused kernel. Block (band, b): MSE partial for 16 output rows of image b
// vs bilinear-upsampled target. band==0 blocks also handle 256 stations of
// batch b. Last finishing block combines, writes 3 outputs, resets globals.
__global__ __launch_bounds__(256, 2) void fused_kernel(const float* __restrict__ pred,
                                                       const float* __restrict__ tgt,
                                                       const int* __restrict__ pos,
                                                       const float* __restrict__ run,
                                                       float* __restrict__ out) {
    __shared__ float st[10][TW];   // 20 KB target row staging
    __shared__ float wsum[8];
    __shared__ float wsum2[8];

    const int band = blockIdx.x;   // 0..63
    const int b    = blockIdx.y;   // 0..31
    const int tid  = threadIdx.x;  // 0..255
    const int kbase = band * 8 - 1;

    // ---- Kick off target staging via cp.async (no register round-trip) ----
    const float* tb = tgt + (size_t)b * TH * TW;
#pragma unroll
    for (int i = 0; i < 5; ++i) {
        int idx = tid + i * 256;          // 0..1279 float4 slots
        int r   = idx >> 7;               // 0..9
        int c4  = (idx & 127) << 2;       // 0..508
        int k   = kbase + r;
        k = k < 0 ? 0 : (k > TH - 1 ? TH - 1 : k);
        cp_async16(&st[r][c4], tb + (size_t)k * TW + c4);
    }
    asm volatile("cp.async.commit_group;");

    // ---- Front-batch ALL 16 pred row loads (max MLP on the 128MB stream) ----
    const float* pb = pred + ((size_t)b * HH + (size_t)band * BAND_ROWS) * WW + 4 * tid;
    float4 P[16];
#pragma unroll
    for (int r = 0; r < 16; ++r)
        P[r] = __ldcs((const float4*)(pb + (size_t)r * WW));

    // ---- Station loss (band==0 blocks only) ----
    float stn_val = 0.f;
    if (band == 0) {
        int idx = b * SS + tid;
        int px = pos[2 * idx];       // column
        int py = pos[2 * idx + 1];   // row
        const float* pb0 = pred + (size_t)b * HH * WW;
        float sum = 0.f;
        int cnt = 0;
#pragma unroll
        for (int dy = -1; dy <= 1; ++dy) {
            int y = py + dy;
            if ((unsigned)y < (unsigned)HH) {
#pragma unroll
                for (int dx = -1; dx <= 1; ++dx) {
                    int x = px + dx;
                    if ((unsigned)x < (unsigned)WW) {
                        sum += pb0[(size_t)y * WW + x];
                        cnt++;
                    }
                }
            }
        }
        float d = sum / (float)cnt - run[idx];
        stn_val = d * d;
    }

    // ---- Wait for target staging ----
    asm volatile("cp.async.wait_group 0;");
    __syncthreads();

    // Column indices this thread needs (target cols 2t-1..2t+2, clamped)
    const int t = tid;
    int j0 = 2 * t - 1; if (j0 < 0) j0 = 0;
    const int j1 = 2 * t;
    const int j2 = 2 * t + 1;
    int j3 = 2 * t + 2; if (j3 > TW - 1) j3 = TW - 1;

    float a0 = st[0][j0], a1 = st[0][j1], a2 = st[0][j2], a3 = st[0][j3];
    float b0 = st[1][j0], b1 = st[1][j1], b2 = st[1][j2], b3 = st[1][j3];

    float acc = 0.f;

#pragma unroll
    for (int p = 0; p < 8; ++p) {
        float c0 = st[p + 2][j0], c1 = st[p + 2][j1];
        float c2 = st[p + 2][j2], c3 = st[p + 2][j3];

        // even output row 2p: 0.25*row(p) + 0.75*row(p+1)
        float4 pv = P[2 * p];
        float v0 = 0.25f * a0 + 0.75f * b0;
        float v1 = 0.25f * a1 + 0.75f * b1;
        float v2 = 0.25f * a2 + 0.75f * b2;
        float v3 = 0.25f * a3 + 0.75f * b3;
        float d;
        d = pv.x - (0.25f * v0 + 0.75f * v1); acc = fmaf(d, d, acc);
        d = pv.y - (0.75f * v1 + 0.25f * v2); acc = fmaf(d, d, acc);
        d = pv.z - (0.25f * v1 + 0.75f * v2); acc = fmaf(d, d, acc);
        d = pv.w - (0.75f * v2 + 0.25f * v3); acc = fmaf(d, d, acc);

        // odd output row 2p+1: 0.75*row(p+1) + 0.25*row(p+2)
        pv = P[2 * p + 1];
        v0 = 0.75f * b0 + 0.25f * c0;
        v1 = 0.75f * b1 + 0.25f * c1;
        v2 = 0.75f * b2 + 0.25f * c2;
        v3 = 0.75f * b3 + 0.25f * c3;
        d = pv.x - (0.25f * v0 + 0.75f * v1); acc = fmaf(d, d, acc);
        d = pv.y - (0.75f * v1 + 0.25f * v2); acc = fmaf(d, d, acc);
        d = pv.z - (0.25f * v1 + 0.75f * v2); acc = fmaf(d, d, acc);
        d = pv.w - (0.75f * v2 + 0.25f * v3); acc = fmaf(d, d, acc);

        a0 = b0; a1 = b1; a2 = b2; a3 = b3;
        b0 = c0; b1 = c1; b2 = c2; b3 = c3;
    }

    // ---- Block reductions ----
#pragma unroll
    for (int o = 16; o > 0; o >>= 1) {
        acc     += __shfl_xor_sync(0xffffffffu, acc, o);
        stn_val += __shfl_xor_sync(0xffffffffu, stn_val, o);
    }
    int lane = tid & 31, wid = tid >> 5;
    if (lane == 0) { wsum[wid] = acc; wsum2[wid] = stn_val; }
    __syncthreads();

    if (tid == 0) {
        float s = 0.f, s2 = 0.f;
#pragma unroll
        for (int i = 0; i < 8; ++i) { s += wsum[i]; s2 += wsum2[i]; }
        atomicAdd(&g_img_sum, (double)s);
        if (band == 0) atomicAdd(&g_stn_sum, (double)s2);
        __threadfence();
        unsigned int old = atomicAdd(&g_count, 1u);
        if (old == NBLOCKS - 1) {
            double img = atomicAdd(&g_img_sum, 0.0) / (double)((size_t)BB * HH * WW);
            double stn = atomicAdd(&g_stn_sum, 0.0) / (double)(BB * SS);
            out[0] = (float)(img + 0.5 * stn);  // IMAGE_W=1.0, STATION_W=0.5
            out[1] = (float)img;
            out[2] = (float)stn;
            g_img_sum = 0.0;
            g_stn_sum = 0.0;
            __threadfence();
            g_count = 0u;
        }
    }
}

extern "C" void kernel_launch(void* const* d_in, const int* in_sizes, int n_in,
                              void* d_out, int out_size) {
    const float* pred = (const float*)d_in[0];   // (32,1,1024,1024) f32
    const float* tgt  = (const float*)d_in[1];   // (32,1,512,512) f32
    const int*   pos  = (const int*)d_in[2];     // (32,256,2) i32
    const float* run  = (const float*)d_in[3];   // (32,256) f32
    float* out = (float*)d_out;

    fused_kernel<<<dim3(NBANDS, BB), 256>>>(pred, tgt, pos, run, out);
}

// round 6
// speedup vs baseline: 1.2895x; 1.0779x over previous
#include <cuda_runtime.h>
#include <cstdint>

// Problem shapes (fixed per reference setup_inputs)
#define BB 32
#define HH 1024
#define WW 1024
#define TH 512
#define TW 512
#define SS 256
#define BAND_ROWS 16               // output rows per block
#define NBANDS (HH / BAND_ROWS)    // 64
#define NBLOCKS (NBANDS * 2 * BB)  // 4096 (x = band*2 + half)
#define STCOLS 264                 // staged target cols per half (4 halo + 258 + pad)
#define STSLOTS 66                 // float4 slots per row

__device__ double g_img_sum = 0.0;
__device__ double g_stn_sum = 0.0;
__device__ unsigned int g_count = 0;

__device__ __forceinline__ void cp_async16(void* smem_dst, const void* gmem_src) {
    uint32_t s = (uint32_t)__cvta_generic_to_shared(smem_dst);
    asm volatile("cp.async.cg.shared.global [%0], [%1], 16;" :: "r"(s), "l"(gmem_src));
}

// Block (x=band*2+half, b): MSE partial for 16 output rows x 512 cols of image
// b vs bilinear-upsampled target. Each thread: 2 output cols x 16 rows.
// Blocks with x==0 also handle the 256 stations of batch b.
__global__ __launch_bounds__(256, 4) void fused_kernel(const float* __restrict__ pred,
                                                       const float* __restrict__ tgt,
                                                       const int* __restrict__ pos,
                                                       const float* __restrict__ run,
                                                       float* __restrict__ out) {
    __shared__ float st[10][STCOLS];   // ~10.6 KB target staging
    __shared__ float wsum[8];
    __shared__ float wsum2[8];

    const int band = blockIdx.x >> 1;    // 0..63
    const int h    = blockIdx.x & 1;     // half: 0 or 1
    const int b    = blockIdx.y;         // 0..31
    const int tid  = threadIdx.x;        // 0..255
    const int kbase = band * 8 - 1;
    const int cbase = 256 * h - 4;       // global target col of smem idx 0

    // ---- Stage 10 target rows x 66 float4 via cp.async ----
    const float* tb = tgt + (size_t)b * TH * TW;
#pragma unroll
    for (int i = 0; i < 3; ++i) {
        int idx = tid + i * 256;              // 0..659
        if (idx < 10 * STSLOTS) {
            int r = idx / STSLOTS;            // 0..9
            int s = idx - r * STSLOTS;        // 0..65
            int k = kbase + r;
            k = k < 0 ? 0 : (k > TH - 1 ? TH - 1 : k);
            int c = cbase + 4 * s;            // may be OOB at edges
            c = c < 0 ? 0 : (c > TW - 4 ? TW - 4 : c);  // clamped slots are never read
            cp_async16(&st[r][4 * s], tb + (size_t)k * TW + c);
        }
    }
    asm volatile("cp.async.commit_group;");

    // ---- Front-batch ALL 16 pred row loads (float2, coalesced) ----
    const float* pb = pred + ((size_t)b * HH + (size_t)band * BAND_ROWS) * WW
                      + 512 * h + 2 * tid;
    float2 P[16];
#pragma unroll
    for (int r = 0; r < 16; ++r)
        P[r] = __ldcs((const float2*)(pb + (size_t)r * WW));

    // ---- Station loss (blockIdx.x==0 blocks only) ----
    float stn_val = 0.f;
    if (blockIdx.x == 0) {
        int idx = b * SS + tid;
        int px = pos[2 * idx];       // column
        int py = pos[2 * idx + 1];   // row
        const float* pb0 = pred + (size_t)b * HH * WW;
        float sum = 0.f;
        int cnt = 0;
#pragma unroll
        for (int dy = -1; dy <= 1; ++dy) {
            int y = py + dy;
            if ((unsigned)y < (unsigned)HH) {
#pragma unroll
                for (int dx = -1; dx <= 1; ++dx) {
                    int x = px + dx;
                    if ((unsigned)x < (unsigned)WW) {
                        sum += pb0[(size_t)y * WW + x];
                        cnt++;
                    }
                }
            }
        }
        float d = sum / (float)cnt - run[idx];
        stn_val = d * d;
    }

    asm volatile("cp.async.wait_group 0;");
    __syncthreads();

    // Target col this thread blends around: k = 256h + tid
    const int kcol = 256 * h + tid;
    int gm = kcol - 1; if (gm < 0) gm = 0;
    int gp = kcol + 1; if (gp > TW - 1) gp = TW - 1;
    const int jm = gm - cbase;
    const int j  = kcol - cbase;       // tid + 4
    const int jp = gp - cbase;

    float am = st[0][jm], a0 = st[0][j], ap = st[0][jp];
    float bm = st[1][jm], b0 = st[1][j], bp = st[1][jp];

    float acc = 0.f;

#pragma unroll
    for (int p = 0; p < 8; ++p) {
        float cm = st[p + 2][jm], c0 = st[p + 2][j], cp = st[p + 2][jp];

        // even output row 2p: vertical 0.25*row(p) + 0.75*row(p+1)
        float2 pv = P[2 * p];
        float vm = 0.25f * am + 0.75f * bm;
        float v0 = 0.25f * a0 + 0.75f * b0;
        float vp = 0.25f * ap + 0.75f * bp;
        float d;
        d = pv.x - (0.25f * vm + 0.75f * v0); acc = fmaf(d, d, acc);
        d = pv.y - (0.75f * v0 + 0.25f * vp); acc = fmaf(d, d, acc);

        // odd output row 2p+1: vertical 0.75*row(p+1) + 0.25*row(p+2)
        pv = P[2 * p + 1];
        vm = 0.75f * bm + 0.25f * cm;
        v0 = 0.75f * b0 + 0.25f * c0;
        vp = 0.75f * bp + 0.25f * cp;
        d = pv.x - (0.25f * vm + 0.75f * v0); acc = fmaf(d, d, acc);
        d = pv.y - (0.75f * v0 + 0.25f * vp); acc = fmaf(d, d, acc);

        am = bm; a0 = b0; ap = bp;
        bm = cm; b0 = c0; bp = cp;
    }

    // ---- Block reductions ----
#pragma unroll
    for (int o = 16; o > 0; o >>= 1) {
        acc     += __shfl_xor_sync(0xffffffffu, acc, o);
        stn_val += __shfl_xor_sync(0xffffffffu, stn_val, o);
    }
    int lane = tid & 31, wid = tid >> 5;
    if (lane == 0) { wsum[wid] = acc; wsum2[wid] = stn_val; }
    __syncthreads();

    if (tid == 0) {
        float s = 0.f, s2 = 0.f;
#pragma unroll
        for (int i = 0; i < 8; ++i) { s += wsum[i]; s2 += wsum2[i]; }
        atomicAdd(&g_img_sum, (double)s);
        if (blockIdx.x == 0) atomicAdd(&g_stn_sum, (double)s2);
        __threadfence();
        unsigned int old = atomicAdd(&g_count, 1u);
        if (old == NBLOCKS - 1) {
            double img = atomicAdd(&g_img_sum, 0.0) / (double)((size_t)BB * HH * WW);
            double stn = atomicAdd(&g_stn_sum, 0.0) / (double)(BB * SS);
            out[0] = (float)(img + 0.5 * stn);  // IMAGE_W=1.0, STATION_W=0.5
            out[1] = (float)img;
            out[2] = (float)stn;
            g_img_sum = 0.0;
            g_stn_sum = 0.0;
            __threadfence();
            g_count = 0u;
        }
    }
}

extern "C" void kernel_launch(void* const* d_in, const int* in_sizes, int n_in,
                              void* d_out, int out_size) {
    const float* pred = (const float*)d_in[0];   // (32,1,1024,1024) f32
    const float* tgt  = (const float*)d_in[1];   // (32,1,512,512) f32
    const int*   pos  = (const int*)d_in[2];     // (32,256,2) i32
    const float* run  = (const float*)d_in[3];   // (32,256) f32
    float* out = (float*)d_out;

    fused_kernel<<<dim3(NBANDS * 2, BB), 256>>>(pred, tgt, pos, run, out);
}